// round 14
// baseline (speedup 1.0000x reference)
#include <cuda_runtime.h>
#include <cuda_fp16.h>
#include <cstdint>

// B=131072, IN_DIM=128, N_NODES=511(pad 512), N_LEAVES=512, N_ACTIONS=16
// 64 rows/CTA, 512 threads (16 warps -> 4 warps/SMSP).
// P1 dense fp16 (W1 hi+lo). P2 sparse 2:4 mma.sp m16n8k32, W2 hi-only.
// Interleaved pipeline: P1(s+1) || P2(s), one barrier per slab.
#define XH_   0
#define Z0_   16384     // |h| 8KB @+0, sign bytes 4KB @+8192
#define Z1_   28672
#define ACT_  40960
#define POOL_ 41472
#define SMEMB 45568

__device__ __align__(16) unsigned char g_w2f[1048576]; // 2048 sparse-B hi frags x 512B
__device__ __align__(16) unsigned char g_w1f[262144];  // 512 frag-blocks x 512B
__device__ float g_b1p[512];

__device__ __forceinline__ uint32_t s2u(const void* p) {
    uint32_t a;
    asm("{ .reg .u64 t; cvta.to.shared.u64 t, %1; cvt.u32.u64 %0, t; }" : "=r"(a) : "l"(p));
    return a;
}
__device__ __forceinline__ uint32_t pk2(float a, float b) {
    __half ah = __float2half_rn(a), bh = __float2half_rn(b);
    return (uint32_t)*(uint16_t*)&ah | ((uint32_t)*(uint16_t*)&bh << 16);
}
__device__ __forceinline__ void sp2f(float a, float b, uint32_t& h, uint32_t& l) {
    __half ah = __float2half_rn(a), bh = __float2half_rn(b);
    __half al = __float2half_rn(a - __half2float(ah));
    __half bl = __float2half_rn(b - __half2float(bh));
    h = (uint32_t)*(uint16_t*)&ah | ((uint32_t)*(uint16_t*)&bh << 16);
    l = (uint32_t)*(uint16_t*)&al | ((uint32_t)*(uint16_t*)&bl << 16);
}
__device__ __forceinline__ void ldm4(uint32_t* r, uint32_t a) {
    asm volatile("ldmatrix.sync.aligned.m8n8.x4.shared.b16 {%0,%1,%2,%3}, [%4];"
                 : "=r"(r[0]), "=r"(r[1]), "=r"(r[2]), "=r"(r[3]) : "r"(a));
}
__device__ __forceinline__ void mma(float* d, const uint32_t* a, const uint32_t* b) {
    asm volatile(
        "mma.sync.aligned.m16n8k16.row.col.f32.f16.f16.f32 "
        "{%0,%1,%2,%3}, {%4,%5,%6,%7}, {%8,%9}, {%0,%1,%2,%3};"
        : "+f"(d[0]), "+f"(d[1]), "+f"(d[2]), "+f"(d[3])
        : "r"(a[0]), "r"(a[1]), "r"(a[2]), "r"(a[3]), "r"(b[0]), "r"(b[1]));
}
__device__ __forceinline__ void mma_sp(float* d, const uint32_t* a, const uint4 b,
                                       uint32_t e) {
    asm volatile(
        "mma.sp::ordered_metadata.sync.aligned.m16n8k32.row.col.f32.f16.f16.f32 "
        "{%0,%1,%2,%3}, {%4,%5,%6,%7}, {%8,%9,%10,%11}, {%0,%1,%2,%3}, %12, 0x0;"
        : "+f"(d[0]), "+f"(d[1]), "+f"(d[2]), "+f"(d[3])
        : "r"(a[0]), "r"(a[1]), "r"(a[2]), "r"(a[3]),
          "r"(b.x), "r"(b.y), "r"(b.z), "r"(b.w), "r"(e));
}
// 8 sign bytes (two u32, each byte 0/1) -> 16-bit metadata (4 nibbles):
// nibble g = s_{2g} | (2+s_{2g+1})<<2
__device__ __forceinline__ uint32_t exp16(uint32_t x0, uint32_t x1) {
    uint32_t m0 = (x0 | (x0 >> 6) | (x0 >> 12) | (x0 >> 18)) & 0xFFu;
    uint32_t m1 = (x1 | (x1 >> 6) | (x1 >> 12) | (x1 >> 18)) & 0xFFu;
    return 0x8888u | m0 | (m1 << 8);
}
__device__ __forceinline__ unsigned ford(float f) {
    unsigned u = __float_as_uint(f);
    return (u & 0x80000000u) ? ~u : (u | 0x80000000u);
}
__device__ __forceinline__ float funord(unsigned s) {
    return __uint_as_float((s & 0x80000000u) ? (s ^ 0x80000000u) : ~s);
}

// ---- prep: W1 dense hi/lo frags; W2 sparse-B hi-only frags (unchanged) ----
__global__ void dtnet_prep(const float* __restrict__ W1, const float* __restrict__ b1,
                           const float* __restrict__ W2) {
    int idx = blockIdx.x * 256 + threadIdx.x;
    int lane = idx & 31;
    if (idx < 65536) {            // W2 sparse frags 0..2047: [s][ks][nt], 512B each
        int frag = idx >> 5;
        int s = frag >> 8, ks = (frag >> 6) & 3, nt = frag & 63;
        int l = nt * 8 + (lane >> 2);
        uint32_t hw[4];
        #pragma unroll
        for (int i = 0; i < 4; i++) {
            int k0 = i * 8 + (lane & 3) * 2;
            float v[2];
            #pragma unroll
            for (int j = 0; j < 2; j++) {
                int k = k0 + j;
                int n = s * 64 + ks * 16 + (k >> 1);
                int c = (k & 1) ? (511 + n) : n;
                v[j] = (n < 511) ? W2[(size_t)l * 1022 + c] : 0.0f;
            }
            hw[i] = pk2(v[0], v[1]);
        }
        *(uint4*)(g_w2f + (size_t)frag * 512 + lane * 16) =
            make_uint4(hw[0], hw[1], hw[2], hw[3]);
    } else if (idx < 81920) {     // W1 frags 0..511 (hi+lo)
        int f2 = (idx >> 5) - 2048;
        int s = f2 >> 6, kt = (f2 >> 3) & 7, nt = f2 & 7;
        int g = s * 64 + nt * 8 + (lane >> 2), k0 = kt * 16 + (lane & 3) * 2;
        const int dd[4] = {0, 1, 8, 9};
        float v[4];
        #pragma unroll
        for (int j = 0; j < 4; j++)
            v[j] = (g < 511) ? W1[(size_t)g * 128 + k0 + dd[j]] : 0.0f;
        uint32_t h0, l0, h1, l1;
        sp2f(v[0], v[1], h0, l0); sp2f(v[2], v[3], h1, l1);
        *(uint4*)(g_w1f + (size_t)f2 * 512 + lane * 16) = make_uint4(h0, h1, l0, l1);
    }
    if (idx < 512) g_b1p[idx] = (idx < 511) ? b1[idx] : 0.0f;
}

// ---- phase 1: H(64x64) slab s -> |h| fp16 + sign bytes. 16 warps:
//      row-tile = w&3, node-group (2 nt) = w>>2 ----
__device__ __forceinline__ void phase1(unsigned char* smc, uint32_t sb, int s,
                                       int w, int lane, uint32_t zbase) {
    float hacc[2][4];
    #pragma unroll
    for (int a = 0; a < 2; a++)
        #pragma unroll
        for (int c = 0; c < 4; c++) hacc[a][c] = 0.0f;
    const int arow = (w & 3) * 16 + (lane & 7) + ((lane >> 3) & 1) * 8;
    #pragma unroll
    for (int kt = 0; kt < 8; kt++) {
        int cc = kt * 2 + (lane >> 4);
        uint32_t ao = arow * 256 + ((cc & 8) | ((cc ^ arow) & 7)) * 16;
        uint32_t ah[4];
        ldm4(ah, sb + XH_ + ao);
        uint4 t1[2];
        #pragma unroll
        for (int ntl = 0; ntl < 2; ntl++)
            t1[ntl] = *(const uint4*)(g_w1f +
                ((size_t)((s * 8 + kt) * 8 + (w >> 2) * 2 + ntl) * 512 + lane * 16));
        #pragma unroll
        for (int ntl = 0; ntl < 2; ntl++) {
            uint32_t bh[2] = {t1[ntl].x, t1[ntl].y};
            mma(hacc[ntl], ah, bh);
        }
        #pragma unroll
        for (int ntl = 0; ntl < 2; ntl++) {
            uint32_t bl[2] = {t1[ntl].z, t1[ntl].w};
            mma(hacc[ntl], ah, bl);
        }
    }
    #pragma unroll
    for (int ntl = 0; ntl < 2; ntl++) {
        int nt = (w >> 2) * 2 + ntl;
        int nloc = nt * 8 + (lane & 3) * 2, gn = s * 64 + nloc;
        float bb0 = g_b1p[gn], bb1 = g_b1p[gn + 1];
        #pragma unroll
        for (int rh = 0; rh < 2; rh++) {
            int row = (w & 3) * 16 + (lane >> 2) + rh * 8;
            float h0 = hacc[ntl][rh * 2] + bb0, h1 = hacc[ntl][rh * 2 + 1] + bb1;
            uint32_t off = row * 128 + (((nt ^ row) & 7) * 16) + (lane & 3) * 4;
            *(uint32_t*)(smc + zbase + off) = pk2(fabsf(h0), fabsf(h1));
            uint32_t s0 = __float_as_uint(h0) >> 31, s1 = __float_as_uint(h1) >> 31;
            *(uint16_t*)(smc + zbase + 8192 + row * 64 + nloc) =
                (uint16_t)(s0 | (s1 << 8));
        }
    }
}

// ---- phase 2 (sparse, hi-only B): acc += Z(s) . W2slab^T, 32 leaves/warp ----
__device__ __forceinline__ void phase2(unsigned char* smc, uint32_t sb, int s,
                                       int w, int lane, uint32_t zbase,
                                       float acc[4][4][4]) {
    const int quad = lane >> 2, kh = lane & 1;
    const uint32_t sgn = zbase + 8192;
    #pragma unroll
    for (int ks = 0; ks < 4; ks++) {
        uint4 tb[4];
        #pragma unroll
        for (int ntl = 0; ntl < 4; ntl++)
            tb[ntl] = *(const uint4*)(g_w2f +
                ((size_t)((s * 4 + ks) * 64 + w * 4 + ntl) * 512 + lane * 16));
        int cc = ks * 2 + (lane >> 4);
        #pragma unroll
        for (int mt = 0; mt < 4; mt++) {
            int row = mt * 16 + (lane & 7) + ((lane >> 3) & 1) * 8;
            uint32_t ao = row * 128 + (((cc ^ row) & 7) * 16);
            uint32_t a[4];
            ldm4(a, sb + zbase + ao);
            int r0 = mt * 16 + quad;
            uint2 sA = *(const uint2*)(smc + sgn + r0 * 64 + ks * 16 + kh * 8);
            uint2 sB = *(const uint2*)(smc + sgn + (r0 + 8) * 64 + ks * 16 + kh * 8);
            uint32_t e = exp16(sA.x, sA.y) | (exp16(sB.x, sB.y) << 16);
            #pragma unroll
            for (int ntl = 0; ntl < 4; ntl++)
                mma_sp(acc[mt][ntl], a, tb[ntl], e);
        }
    }
}

// ---- main fused kernel: 512 threads ----
__global__ __launch_bounds__(512, 1)
void dtnet_mma(const float* __restrict__ x, const int* __restrict__ la,
               float* __restrict__ out) {
    extern __shared__ unsigned char smc[];
    const uint32_t sb = s2u(smc);
    const int tid = threadIdx.x, w = tid >> 5, lane = tid & 31;
    const int row0 = blockIdx.x * 64;
    unsigned* pool = (unsigned*)(smc + POOL_);
    const uint8_t* act = (const uint8_t*)(smc + ACT_);

    ((uint8_t*)(smc + ACT_))[tid] = (uint8_t)la[tid];
    for (int i = tid; i < 1024; i += 512) pool[i] = 0u;

    // stage X [64 x 128] fp16-hi, swizzled 256B rows
    #pragma unroll
    for (int it = 0; it < 4; it++) {
        int idx = it * 512 + tid, r = idx >> 5, q = idx & 31;
        float4 v = ((const float4*)(x + (size_t)(row0 + r) * 128))[q];
        int kb = q >> 1;
        uint32_t off = r * 256 + ((kb & 8) | ((kb ^ r) & 7)) * 16 + (q & 1) * 8;
        *(uint2*)(smc + XH_ + off) = make_uint2(pk2(v.x, v.y), pk2(v.z, v.w));
    }
    __syncthreads();

    float acc[4][4][4];
    #pragma unroll
    for (int a = 0; a < 4; a++)
        #pragma unroll
        for (int b = 0; b < 4; b++)
            #pragma unroll
            for (int c = 0; c < 4; c++) acc[a][b][c] = 0.0f;

    phase1(smc, sb, 0, w, lane, Z0_);
    __syncthreads();

    #pragma unroll 2
    for (int s = 0; s < 8; s++) {
        if (s < 7)
            phase1(smc, sb, s + 1, w, lane, ((s + 1) & 1) ? Z1_ : Z0_);
        phase2(smc, sb, s, w, lane, (s & 1) ? Z1_ : Z0_, acc);
        __syncthreads();
    }

    // ---- epilogue: segment-max + softmax ----
    #pragma unroll
    for (int mt = 0; mt < 4; mt++)
        #pragma unroll
        for (int ntl = 0; ntl < 4; ntl++)
            #pragma unroll
            for (int i = 0; i < 2; i++) {
                int col = w * 32 + ntl * 8 + (lane & 3) * 2 + i;
                int a = act[col];
                #pragma unroll
                for (int rh = 0; rh < 2; rh++) {
                    int row = mt * 16 + (lane >> 2) + rh * 8;
                    atomicMax(&pool[row * 16 + a], ford(acc[mt][ntl][rh * 2 + i]));
                }
            }
    __syncthreads();
    if (tid < 64) {
        float v[16], mx = -3.402823466e38f;
        #pragma unroll
        for (int a = 0; a < 16; a++) {
            v[a] = funord(pool[tid * 16 + a]);
            mx = fmaxf(mx, v[a]);
        }
        float sum = 0.f;
        #pragma unroll
        for (int a = 0; a < 16; a++) { v[a] = __expf(v[a] - mx); sum += v[a]; }
        float inv = 1.f / sum;
        float4* o = (float4*)(out + (size_t)(row0 + tid) * 16);
        o[0] = make_float4(v[0] * inv, v[1] * inv, v[2] * inv, v[3] * inv);
        o[1] = make_float4(v[4] * inv, v[5] * inv, v[6] * inv, v[7] * inv);
        o[2] = make_float4(v[8] * inv, v[9] * inv, v[10] * inv, v[11] * inv);
        o[3] = make_float4(v[12] * inv, v[13] * inv, v[14] * inv, v[15] * inv);
    }
}

extern "C" void kernel_launch(void* const* d_in, const int* in_sizes, int n_in,
                              void* d_out, int out_size) {
    const float* x  = (const float*)d_in[0];
    const float* W1 = (const float*)d_in[1];
    const float* b1 = (const float*)d_in[2];
    const float* W2 = (const float*)d_in[3];
    const int*   la = (const int*)d_in[4];
    float* out = (float*)d_out;

    dtnet_prep<<<320, 256>>>(W1, b1, W2);
    cudaFuncSetAttribute(dtnet_mma, cudaFuncAttributeMaxDynamicSharedMemorySize, SMEMB);
    int Btot = in_sizes[0] / 128;   // 131072
    dtnet_mma<<<Btot / 64, 512, SMEMB>>>(x, la, out);
}

// round 15
// speedup vs baseline: 1.1537x; 1.1537x over previous
#include <cuda_runtime.h>
#include <cuda_fp16.h>
#include <cstdint>

// B=131072, IN_DIM=128, N_NODES=511(pad 512), N_LEAVES=512, N_ACTIONS=16
// 64 rows/CTA, 512 threads (4 warps/SMSP).
// P2 warp split: row-half = w&1 (2 mt), leaf-group = w>>1 (8 ntl) -> total
// A-fragment + metadata work identical to the 256-thread R13 kernel.
#define XH_   0
#define Z0_   16384     // |h| 8KB @+0, sign bytes 4KB @+8192
#define Z1_   28672
#define ACT_  40960
#define POOL_ 41472
#define SMEMB 45568

__device__ __align__(16) unsigned char g_w2f[1048576]; // 2048 sparse-B hi frags x 512B
__device__ __align__(16) unsigned char g_w1f[262144];  // 512 frag-blocks x 512B
__device__ float g_b1p[512];

__device__ __forceinline__ uint32_t s2u(const void* p) {
    uint32_t a;
    asm("{ .reg .u64 t; cvta.to.shared.u64 t, %1; cvt.u32.u64 %0, t; }" : "=r"(a) : "l"(p));
    return a;
}
__device__ __forceinline__ uint32_t pk2(float a, float b) {
    __half ah = __float2half_rn(a), bh = __float2half_rn(b);
    return (uint32_t)*(uint16_t*)&ah | ((uint32_t)*(uint16_t*)&bh << 16);
}
__device__ __forceinline__ void sp2f(float a, float b, uint32_t& h, uint32_t& l) {
    __half ah = __float2half_rn(a), bh = __float2half_rn(b);
    __half al = __float2half_rn(a - __half2float(ah));
    __half bl = __float2half_rn(b - __half2float(bh));
    h = (uint32_t)*(uint16_t*)&ah | ((uint32_t)*(uint16_t*)&bh << 16);
    l = (uint32_t)*(uint16_t*)&al | ((uint32_t)*(uint16_t*)&bl << 16);
}
__device__ __forceinline__ void ldm4(uint32_t* r, uint32_t a) {
    asm volatile("ldmatrix.sync.aligned.m8n8.x4.shared.b16 {%0,%1,%2,%3}, [%4];"
                 : "=r"(r[0]), "=r"(r[1]), "=r"(r[2]), "=r"(r[3]) : "r"(a));
}
__device__ __forceinline__ void mma(float* d, const uint32_t* a, const uint32_t* b) {
    asm volatile(
        "mma.sync.aligned.m16n8k16.row.col.f32.f16.f16.f32 "
        "{%0,%1,%2,%3}, {%4,%5,%6,%7}, {%8,%9}, {%0,%1,%2,%3};"
        : "+f"(d[0]), "+f"(d[1]), "+f"(d[2]), "+f"(d[3])
        : "r"(a[0]), "r"(a[1]), "r"(a[2]), "r"(a[3]), "r"(b[0]), "r"(b[1]));
}
__device__ __forceinline__ void mma_sp(float* d, const uint32_t* a, const uint4 b,
                                       uint32_t e) {
    asm volatile(
        "mma.sp::ordered_metadata.sync.aligned.m16n8k32.row.col.f32.f16.f16.f32 "
        "{%0,%1,%2,%3}, {%4,%5,%6,%7}, {%8,%9,%10,%11}, {%0,%1,%2,%3}, %12, 0x0;"
        : "+f"(d[0]), "+f"(d[1]), "+f"(d[2]), "+f"(d[3])
        : "r"(a[0]), "r"(a[1]), "r"(a[2]), "r"(a[3]),
          "r"(b.x), "r"(b.y), "r"(b.z), "r"(b.w), "r"(e));
}
// 8 sign bytes (two u32, each byte 0/1) -> 16-bit metadata (4 nibbles)
__device__ __forceinline__ uint32_t exp16(uint32_t x0, uint32_t x1) {
    uint32_t m0 = (x0 | (x0 >> 6) | (x0 >> 12) | (x0 >> 18)) & 0xFFu;
    uint32_t m1 = (x1 | (x1 >> 6) | (x1 >> 12) | (x1 >> 18)) & 0xFFu;
    return 0x8888u | m0 | (m1 << 8);
}
__device__ __forceinline__ unsigned ford(float f) {
    unsigned u = __float_as_uint(f);
    return (u & 0x80000000u) ? ~u : (u | 0x80000000u);
}
__device__ __forceinline__ float funord(unsigned s) {
    return __uint_as_float((s & 0x80000000u) ? (s ^ 0x80000000u) : ~s);
}

// ---- prep: W1 dense hi/lo frags; W2 sparse-B hi-only frags (unchanged) ----
__global__ void dtnet_prep(const float* __restrict__ W1, const float* __restrict__ b1,
                           const float* __restrict__ W2) {
    int idx = blockIdx.x * 256 + threadIdx.x;
    int lane = idx & 31;
    if (idx < 65536) {            // W2 sparse frags 0..2047: [s][ks][nt], 512B each
        int frag = idx >> 5;
        int s = frag >> 8, ks = (frag >> 6) & 3, nt = frag & 63;
        int l = nt * 8 + (lane >> 2);
        uint32_t hw[4];
        #pragma unroll
        for (int i = 0; i < 4; i++) {
            int k0 = i * 8 + (lane & 3) * 2;
            float v[2];
            #pragma unroll
            for (int j = 0; j < 2; j++) {
                int k = k0 + j;
                int n = s * 64 + ks * 16 + (k >> 1);
                int c = (k & 1) ? (511 + n) : n;
                v[j] = (n < 511) ? W2[(size_t)l * 1022 + c] : 0.0f;
            }
            hw[i] = pk2(v[0], v[1]);
        }
        *(uint4*)(g_w2f + (size_t)frag * 512 + lane * 16) =
            make_uint4(hw[0], hw[1], hw[2], hw[3]);
    } else if (idx < 81920) {     // W1 frags 0..511 (hi+lo)
        int f2 = (idx >> 5) - 2048;
        int s = f2 >> 6, kt = (f2 >> 3) & 7, nt = f2 & 7;
        int g = s * 64 + nt * 8 + (lane >> 2), k0 = kt * 16 + (lane & 3) * 2;
        const int dd[4] = {0, 1, 8, 9};
        float v[4];
        #pragma unroll
        for (int j = 0; j < 4; j++)
            v[j] = (g < 511) ? W1[(size_t)g * 128 + k0 + dd[j]] : 0.0f;
        uint32_t h0, l0, h1, l1;
        sp2f(v[0], v[1], h0, l0); sp2f(v[2], v[3], h1, l1);
        *(uint4*)(g_w1f + (size_t)f2 * 512 + lane * 16) = make_uint4(h0, h1, l0, l1);
    }
    if (idx < 512) g_b1p[idx] = (idx < 511) ? b1[idx] : 0.0f;
}

// ---- phase 1: H(64x64) slab s -> |h| fp16 + sign bytes. 16 warps:
//      row-tile = w&3, node-group (2 nt) = w>>2 ----
__device__ __forceinline__ void phase1(unsigned char* smc, uint32_t sb, int s,
                                       int w, int lane, uint32_t zbase) {
    float hacc[2][4];
    #pragma unroll
    for (int a = 0; a < 2; a++)
        #pragma unroll
        for (int c = 0; c < 4; c++) hacc[a][c] = 0.0f;
    const int arow = (w & 3) * 16 + (lane & 7) + ((lane >> 3) & 1) * 8;
    #pragma unroll
    for (int kt = 0; kt < 8; kt++) {
        int cc = kt * 2 + (lane >> 4);
        uint32_t ao = arow * 256 + ((cc & 8) | ((cc ^ arow) & 7)) * 16;
        uint32_t ah[4];
        ldm4(ah, sb + XH_ + ao);
        uint4 t1[2];
        #pragma unroll
        for (int ntl = 0; ntl < 2; ntl++)
            t1[ntl] = *(const uint4*)(g_w1f +
                ((size_t)((s * 8 + kt) * 8 + (w >> 2) * 2 + ntl) * 512 + lane * 16));
        #pragma unroll
        for (int ntl = 0; ntl < 2; ntl++) {
            uint32_t bh[2] = {t1[ntl].x, t1[ntl].y};
            mma(hacc[ntl], ah, bh);
        }
        #pragma unroll
        for (int ntl = 0; ntl < 2; ntl++) {
            uint32_t bl[2] = {t1[ntl].z, t1[ntl].w};
            mma(hacc[ntl], ah, bl);
        }
    }
    #pragma unroll
    for (int ntl = 0; ntl < 2; ntl++) {
        int nt = (w >> 2) * 2 + ntl;
        int nloc = nt * 8 + (lane & 3) * 2, gn = s * 64 + nloc;
        float bb0 = g_b1p[gn], bb1 = g_b1p[gn + 1];
        #pragma unroll
        for (int rh = 0; rh < 2; rh++) {
            int row = (w & 3) * 16 + (lane >> 2) + rh * 8;
            float h0 = hacc[ntl][rh * 2] + bb0, h1 = hacc[ntl][rh * 2 + 1] + bb1;
            uint32_t off = row * 128 + (((nt ^ row) & 7) * 16) + (lane & 3) * 4;
            *(uint32_t*)(smc + zbase + off) = pk2(fabsf(h0), fabsf(h1));
            uint32_t s0 = __float_as_uint(h0) >> 31, s1 = __float_as_uint(h1) >> 31;
            *(uint16_t*)(smc + zbase + 8192 + row * 64 + nloc) =
                (uint16_t)(s0 | (s1 << 8));
        }
    }
}

// ---- phase 2 (sparse, hi-only B): rows (w&1)*32..+31, leaves (w>>1)*64..+63 ----
__device__ __forceinline__ void phase2(unsigned char* smc, uint32_t sb, int s,
                                       int w, int lane, uint32_t zbase,
                                       float acc[2][8][4]) {
    const int quad = lane >> 2, kh = lane & 1;
    const int rbase = (w & 1) * 32, lg = w >> 1;
    const uint32_t sgn = zbase + 8192;
    #pragma unroll
    for (int ks = 0; ks < 4; ks++) {
        uint32_t a[2][4], e[2];
        int cc = ks * 2 + (lane >> 4);
        #pragma unroll
        for (int mt = 0; mt < 2; mt++) {
            int row = rbase + mt * 16 + (lane & 7) + ((lane >> 3) & 1) * 8;
            uint32_t ao = row * 128 + (((cc ^ row) & 7) * 16);
            ldm4(a[mt], sb + zbase + ao);
            int r0 = rbase + mt * 16 + quad;
            uint2 sA = *(const uint2*)(smc + sgn + r0 * 64 + ks * 16 + kh * 8);
            uint2 sB = *(const uint2*)(smc + sgn + (r0 + 8) * 64 + ks * 16 + kh * 8);
            e[mt] = exp16(sA.x, sA.y) | (exp16(sB.x, sB.y) << 16);
        }
        #pragma unroll
        for (int g = 0; g < 2; g++) {
            uint4 tb[4];
            #pragma unroll
            for (int ntl = 0; ntl < 4; ntl++)
                tb[ntl] = *(const uint4*)(g_w2f +
                    ((size_t)((s * 4 + ks) * 64 + lg * 8 + g * 4 + ntl) * 512
                     + lane * 16));
            #pragma unroll
            for (int mt = 0; mt < 2; mt++)
                #pragma unroll
                for (int ntl = 0; ntl < 4; ntl++)
                    mma_sp(acc[mt][g * 4 + ntl], a[mt], tb[ntl], e[mt]);
        }
    }
}

// ---- main fused kernel: 512 threads ----
__global__ __launch_bounds__(512, 1)
void dtnet_mma(const float* __restrict__ x, const int* __restrict__ la,
               float* __restrict__ out) {
    extern __shared__ unsigned char smc[];
    const uint32_t sb = s2u(smc);
    const int tid = threadIdx.x, w = tid >> 5, lane = tid & 31;
    const int row0 = blockIdx.x * 64;
    unsigned* pool = (unsigned*)(smc + POOL_);
    const uint8_t* act = (const uint8_t*)(smc + ACT_);

    ((uint8_t*)(smc + ACT_))[tid] = (uint8_t)la[tid];
    for (int i = tid; i < 1024; i += 512) pool[i] = 0u;

    // stage X [64 x 128] fp16-hi, swizzled 256B rows
    #pragma unroll
    for (int it = 0; it < 4; it++) {
        int idx = it * 512 + tid, r = idx >> 5, q = idx & 31;
        float4 v = ((const float4*)(x + (size_t)(row0 + r) * 128))[q];
        int kb = q >> 1;
        uint32_t off = r * 256 + ((kb & 8) | ((kb ^ r) & 7)) * 16 + (q & 1) * 8;
        *(uint2*)(smc + XH_ + off) = make_uint2(pk2(v.x, v.y), pk2(v.z, v.w));
    }
    __syncthreads();

    float acc[2][8][4];
    #pragma unroll
    for (int a = 0; a < 2; a++)
        #pragma unroll
        for (int b = 0; b < 8; b++)
            #pragma unroll
            for (int c = 0; c < 4; c++) acc[a][b][c] = 0.0f;

    phase1(smc, sb, 0, w, lane, Z0_);
    __syncthreads();

    #pragma unroll 2
    for (int s = 0; s < 8; s++) {
        if (s < 7)
            phase1(smc, sb, s + 1, w, lane, ((s + 1) & 1) ? Z1_ : Z0_);
        phase2(smc, sb, s, w, lane, (s & 1) ? Z1_ : Z0_, acc);
        __syncthreads();
    }

    // ---- epilogue: segment-max + softmax ----
    #pragma unroll
    for (int mt = 0; mt < 2; mt++)
        #pragma unroll
        for (int ntl = 0; ntl < 8; ntl++)
            #pragma unroll
            for (int i = 0; i < 2; i++) {
                int col = (w >> 1) * 64 + ntl * 8 + (lane & 3) * 2 + i;
                int a = act[col];
                #pragma unroll
                for (int rh = 0; rh < 2; rh++) {
                    int row = (w & 1) * 32 + mt * 16 + (lane >> 2) + rh * 8;
                    atomicMax(&pool[row * 16 + a], ford(acc[mt][ntl][rh * 2 + i]));
                }
            }
    __syncthreads();
    if (tid < 64) {
        float v[16], mx = -3.402823466e38f;
        #pragma unroll
        for (int a = 0; a < 16; a++) {
            v[a] = funord(pool[tid * 16 + a]);
            mx = fmaxf(mx, v[a]);
        }
        float sum = 0.f;
        #pragma unroll
        for (int a = 0; a < 16; a++) { v[a] = __expf(v[a] - mx); sum += v[a]; }
        float inv = 1.f / sum;
        float4* o = (float4*)(out + (size_t)(row0 + tid) * 16);
        o[0] = make_float4(v[0] * inv, v[1] * inv, v[2] * inv, v[3] * inv);
        o[1] = make_float4(v[4] * inv, v[5] * inv, v[6] * inv, v[7] * inv);
        o[2] = make_float4(v[8] * inv, v[9] * inv, v[10] * inv, v[11] * inv);
        o[3] = make_float4(v[12] * inv, v[13] * inv, v[14] * inv, v[15] * inv);
    }
}

extern "C" void kernel_launch(void* const* d_in, const int* in_sizes, int n_in,
                              void* d_out, int out_size) {
    const float* x  = (const float*)d_in[0];
    const float* W1 = (const float*)d_in[1];
    const float* b1 = (const float*)d_in[2];
    const float* W2 = (const float*)d_in[3];
    const int*   la = (const int*)d_in[4];
    float* out = (float*)d_out;

    dtnet_prep<<<320, 256>>>(W1, b1, W2);
    cudaFuncSetAttribute(dtnet_mma, cudaFuncAttributeMaxDynamicSharedMemorySize, SMEMB);
    int Btot = in_sizes[0] / 128;   // 131072
    dtnet_mma<<<Btot / 64, 512, SMEMB>>>(x, la, out);
}

// round 16
// speedup vs baseline: 1.2658x; 1.0971x over previous
#include <cuda_runtime.h>
#include <cuda_fp16.h>
#include <cstdint>

// B=131072, IN_DIM=128, N_NODES=511(pad 512), N_LEAVES=512, N_ACTIONS=16
// 64 rows/CTA, 512 threads (4 warps/SMSP).
// P1 dense fp16 (W1 hi+lo) + ballot-assembled 2:4 metadata words.
// P2 sparse mma.sp m16n8k32, W2 hi-only, warp = full 64 rows x 32 leaves
// (no tb duplication). Metadata: one LDS.32 per (ks,mt), zero ALU.
#define XH_   0
#define Z0_   16384     // |h| 8KB @+0, metadata 1KB @+8192
#define Z1_   28672
#define ACT_  40960
#define POOL_ 41472
#define SMEMB 45568

__device__ __align__(16) unsigned char g_w2f[1048576]; // 2048 sparse-B hi frags x 512B
__device__ __align__(16) unsigned char g_w1f[262144];  // 512 frag-blocks x 512B
__device__ float g_b1p[512];

__device__ __forceinline__ uint32_t s2u(const void* p) {
    uint32_t a;
    asm("{ .reg .u64 t; cvta.to.shared.u64 t, %1; cvt.u32.u64 %0, t; }" : "=r"(a) : "l"(p));
    return a;
}
__device__ __forceinline__ uint32_t pk2(float a, float b) {
    __half ah = __float2half_rn(a), bh = __float2half_rn(b);
    return (uint32_t)*(uint16_t*)&ah | ((uint32_t)*(uint16_t*)&bh << 16);
}
__device__ __forceinline__ void sp2f(float a, float b, uint32_t& h, uint32_t& l) {
    __half ah = __float2half_rn(a), bh = __float2half_rn(b);
    __half al = __float2half_rn(a - __half2float(ah));
    __half bl = __float2half_rn(b - __half2float(bh));
    h = (uint32_t)*(uint16_t*)&ah | ((uint32_t)*(uint16_t*)&bh << 16);
    l = (uint32_t)*(uint16_t*)&al | ((uint32_t)*(uint16_t*)&bl << 16);
}
__device__ __forceinline__ void ldm4(uint32_t* r, uint32_t a) {
    asm volatile("ldmatrix.sync.aligned.m8n8.x4.shared.b16 {%0,%1,%2,%3}, [%4];"
                 : "=r"(r[0]), "=r"(r[1]), "=r"(r[2]), "=r"(r[3]) : "r"(a));
}
__device__ __forceinline__ void mma(float* d, const uint32_t* a, const uint32_t* b) {
    asm volatile(
        "mma.sync.aligned.m16n8k16.row.col.f32.f16.f16.f32 "
        "{%0,%1,%2,%3}, {%4,%5,%6,%7}, {%8,%9}, {%0,%1,%2,%3};"
        : "+f"(d[0]), "+f"(d[1]), "+f"(d[2]), "+f"(d[3])
        : "r"(a[0]), "r"(a[1]), "r"(a[2]), "r"(a[3]), "r"(b[0]), "r"(b[1]));
}
__device__ __forceinline__ void mma_sp(float* d, const uint32_t* a, const uint4 b,
                                       uint32_t e) {
    asm volatile(
        "mma.sp::ordered_metadata.sync.aligned.m16n8k32.row.col.f32.f16.f16.f32 "
        "{%0,%1,%2,%3}, {%4,%5,%6,%7}, {%8,%9,%10,%11}, {%0,%1,%2,%3}, %12, 0x0;"
        : "+f"(d[0]), "+f"(d[1]), "+f"(d[2]), "+f"(d[3])
        : "r"(a[0]), "r"(a[1]), "r"(a[2]), "r"(a[3]),
          "r"(b.x), "r"(b.y), "r"(b.z), "r"(b.w), "r"(e));
}
// spread 4 bits: bit j -> bit 4j
__device__ __forceinline__ uint32_t spread4(uint32_t x) {
    return (x & 1u) | ((x & 2u) << 3) | ((x & 4u) << 6) | ((x & 8u) << 9);
}
__device__ __forceinline__ unsigned ford(float f) {
    unsigned u = __float_as_uint(f);
    return (u & 0x80000000u) ? ~u : (u | 0x80000000u);
}
__device__ __forceinline__ float funord(unsigned s) {
    return __uint_as_float((s & 0x80000000u) ? (s ^ 0x80000000u) : ~s);
}

// ---- prep: W1 dense hi/lo frags; W2 sparse-B hi-only frags (unchanged) ----
__global__ void dtnet_prep(const float* __restrict__ W1, const float* __restrict__ b1,
                           const float* __restrict__ W2) {
    int idx = blockIdx.x * 256 + threadIdx.x;
    int lane = idx & 31;
    if (idx < 65536) {            // W2 sparse frags 0..2047: [s][ks][nt], 512B each
        int frag = idx >> 5;
        int s = frag >> 8, ks = (frag >> 6) & 3, nt = frag & 63;
        int l = nt * 8 + (lane >> 2);
        uint32_t hw[4];
        #pragma unroll
        for (int i = 0; i < 4; i++) {
            int k0 = i * 8 + (lane & 3) * 2;
            float v[2];
            #pragma unroll
            for (int j = 0; j < 2; j++) {
                int k = k0 + j;
                int n = s * 64 + ks * 16 + (k >> 1);
                int c = (k & 1) ? (511 + n) : n;
                v[j] = (n < 511) ? W2[(size_t)l * 1022 + c] : 0.0f;
            }
            hw[i] = pk2(v[0], v[1]);
        }
        *(uint4*)(g_w2f + (size_t)frag * 512 + lane * 16) =
            make_uint4(hw[0], hw[1], hw[2], hw[3]);
    } else if (idx < 81920) {     // W1 frags 0..511 (hi+lo)
        int f2 = (idx >> 5) - 2048;
        int s = f2 >> 6, kt = (f2 >> 3) & 7, nt = f2 & 7;
        int g = s * 64 + nt * 8 + (lane >> 2), k0 = kt * 16 + (lane & 3) * 2;
        const int dd[4] = {0, 1, 8, 9};
        float v[4];
        #pragma unroll
        for (int j = 0; j < 4; j++)
            v[j] = (g < 511) ? W1[(size_t)g * 128 + k0 + dd[j]] : 0.0f;
        uint32_t h0, l0, h1, l1;
        sp2f(v[0], v[1], h0, l0); sp2f(v[2], v[3], h1, l1);
        *(uint4*)(g_w1f + (size_t)f2 * 512 + lane * 16) = make_uint4(h0, h1, l0, l1);
    }
    if (idx < 512) g_b1p[idx] = (idx < 511) ? b1[idx] : 0.0f;
}

// ---- phase 1: H(64x64) slab s -> |h| fp16 + packed 2:4 metadata words.
//      16 warps: row-tile = w&3, node-group (2 nt) = w>>2 ----
__device__ __forceinline__ void phase1(unsigned char* smc, uint32_t sb, int s,
                                       int w, int lane, uint32_t zbase) {
    float hacc[2][4];
    #pragma unroll
    for (int a = 0; a < 2; a++)
        #pragma unroll
        for (int c = 0; c < 4; c++) hacc[a][c] = 0.0f;
    const int arow = (w & 3) * 16 + (lane & 7) + ((lane >> 3) & 1) * 8;
    #pragma unroll
    for (int kt = 0; kt < 8; kt++) {
        int cc = kt * 2 + (lane >> 4);
        uint32_t ao = arow * 256 + ((cc & 8) | ((cc ^ arow) & 7)) * 16;
        uint32_t ah[4];
        ldm4(ah, sb + XH_ + ao);
        uint4 t1[2];
        #pragma unroll
        for (int ntl = 0; ntl < 2; ntl++)
            t1[ntl] = *(const uint4*)(g_w1f +
                ((size_t)((s * 8 + kt) * 8 + (w >> 2) * 2 + ntl) * 512 + lane * 16));
        #pragma unroll
        for (int ntl = 0; ntl < 2; ntl++) {
            uint32_t bh[2] = {t1[ntl].x, t1[ntl].y};
            mma(hacc[ntl], ah, bh);
        }
        #pragma unroll
        for (int ntl = 0; ntl < 2; ntl++) {
            uint32_t bl[2] = {t1[ntl].z, t1[ntl].w};
            mma(hacc[ntl], ah, bl);
        }
    }
    #pragma unroll
    for (int ntl = 0; ntl < 2; ntl++) {
        int nt = (w >> 2) * 2 + ntl;
        int nloc = nt * 8 + (lane & 3) * 2, gn = s * 64 + nloc;
        float bb0 = g_b1p[gn], bb1 = g_b1p[gn + 1];
        #pragma unroll
        for (int rh = 0; rh < 2; rh++) {
            int row = (w & 3) * 16 + (lane >> 2) + rh * 8;
            float h0 = hacc[ntl][rh * 2] + bb0, h1 = hacc[ntl][rh * 2 + 1] + bb1;
            uint32_t off = row * 128 + (((nt ^ row) & 7) * 16) + (lane & 3) * 4;
            *(uint32_t*)(smc + zbase + off) = pk2(fabsf(h0), fabsf(h1));
            // ballot-assemble 16-bit metadata word for this row / node-group nt
            uint32_t s0 = __float_as_uint(h0) >> 31, s1 = __float_as_uint(h1) >> 31;
            uint32_t b0 = __ballot_sync(0xFFFFFFFFu, s0);
            uint32_t b1v = __ballot_sync(0xFFFFFFFFu, s1);
            uint32_t x0 = (b0 >> (lane & 28)) & 0xFu;
            uint32_t x1 = (b1v >> (lane & 28)) & 0xFu;
            uint32_t e16 = 0x8888u | spread4(x0) | (spread4(x1) << 2);
            if ((lane & 3) == 0)
                *(uint16_t*)(smc + zbase + 8192 + nt * 128 + (lane >> 2) * 16
                             + ((w & 3) * 2 + rh) * 2) = (uint16_t)e16;
        }
    }
}

// ---- phase 2 (sparse, hi-only B): warp = all 64 rows x 32 leaves (w*32..) ----
__device__ __forceinline__ void phase2(unsigned char* smc, uint32_t sb, int s,
                                       int w, int lane, uint32_t zbase,
                                       float acc[4][4][4]) {
    const int quad = lane >> 2;
    const uint32_t meta = zbase + 8192;
    #pragma unroll
    for (int ks = 0; ks < 4; ks++) {
        uint4 tb[4];
        #pragma unroll
        for (int ntl = 0; ntl < 4; ntl++)
            tb[ntl] = *(const uint4*)(g_w2f +
                ((size_t)((s * 4 + ks) * 64 + w * 4 + ntl) * 512 + lane * 16));
        int cc = ks * 2 + (lane >> 4);
        int widx = ks * 2 + (lane & 1);
        #pragma unroll
        for (int mt = 0; mt < 4; mt++) {
            int row = mt * 16 + (lane & 7) + ((lane >> 3) & 1) * 8;
            uint32_t ao = row * 128 + (((cc ^ row) & 7) * 16);
            uint32_t a[4];
            ldm4(a, sb + zbase + ao);
            uint32_t e = *(const uint32_t*)(smc + meta + widx * 128
                                            + quad * 16 + mt * 4);
            #pragma unroll
            for (int ntl = 0; ntl < 4; ntl++)
                mma_sp(acc[mt][ntl], a, tb[ntl], e);
        }
    }
}

// ---- main fused kernel: 512 threads ----
__global__ __launch_bounds__(512, 1)
void dtnet_mma(const float* __restrict__ x, const int* __restrict__ la,
               float* __restrict__ out) {
    extern __shared__ unsigned char smc[];
    const uint32_t sb = s2u(smc);
    const int tid = threadIdx.x, w = tid >> 5, lane = tid & 31;
    const int row0 = blockIdx.x * 64;
    unsigned* pool = (unsigned*)(smc + POOL_);
    const uint8_t* act = (const uint8_t*)(smc + ACT_);

    ((uint8_t*)(smc + ACT_))[tid] = (uint8_t)la[tid];
    for (int i = tid; i < 1024; i += 512) pool[i] = 0u;

    // stage X [64 x 128] fp16-hi, swizzled 256B rows
    #pragma unroll
    for (int it = 0; it < 4; it++) {
        int idx = it * 512 + tid, r = idx >> 5, q = idx & 31;
        float4 v = ((const float4*)(x + (size_t)(row0 + r) * 128))[q];
        int kb = q >> 1;
        uint32_t off = r * 256 + ((kb & 8) | ((kb ^ r) & 7)) * 16 + (q & 1) * 8;
        *(uint2*)(smc + XH_ + off) = make_uint2(pk2(v.x, v.y), pk2(v.z, v.w));
    }
    __syncthreads();

    float acc[4][4][4];
    #pragma unroll
    for (int a = 0; a < 4; a++)
        #pragma unroll
        for (int b = 0; b < 4; b++)
            #pragma unroll
            for (int c = 0; c < 4; c++) acc[a][b][c] = 0.0f;

    phase1(smc, sb, 0, w, lane, Z0_);
    __syncthreads();

    #pragma unroll 2
    for (int s = 0; s < 8; s++) {
        if (s < 7)
            phase1(smc, sb, s + 1, w, lane, ((s + 1) & 1) ? Z1_ : Z0_);
        phase2(smc, sb, s, w, lane, (s & 1) ? Z1_ : Z0_, acc);
        __syncthreads();
    }

    // ---- epilogue: segment-max + softmax ----
    #pragma unroll
    for (int mt = 0; mt < 4; mt++)
        #pragma unroll
        for (int ntl = 0; ntl < 4; ntl++)
            #pragma unroll
            for (int i = 0; i < 2; i++) {
                int col = w * 32 + ntl * 8 + (lane & 3) * 2 + i;
                int a = act[col];
                #pragma unroll
                for (int rh = 0; rh < 2; rh++) {
                    int row = mt * 16 + (lane >> 2) + rh * 8;
                    atomicMax(&pool[row * 16 + a], ford(acc[mt][ntl][rh * 2 + i]));
                }
            }
    __syncthreads();
    if (tid < 64) {
        float v[16], mx = -3.402823466e38f;
        #pragma unroll
        for (int a = 0; a < 16; a++) {
            v[a] = funord(pool[tid * 16 + a]);
            mx = fmaxf(mx, v[a]);
        }
        float sum = 0.f;
        #pragma unroll
        for (int a = 0; a < 16; a++) { v[a] = __expf(v[a] - mx); sum += v[a]; }
        float inv = 1.f / sum;
        float4* o = (float4*)(out + (size_t)(row0 + tid) * 16);
        o[0] = make_float4(v[0] * inv, v[1] * inv, v[2] * inv, v[3] * inv);
        o[1] = make_float4(v[4] * inv, v[5] * inv, v[6] * inv, v[7] * inv);
        o[2] = make_float4(v[8] * inv, v[9] * inv, v[10] * inv, v[11] * inv);
        o[3] = make_float4(v[12] * inv, v[13] * inv, v[14] * inv, v[15] * inv);
    }
}

extern "C" void kernel_launch(void* const* d_in, const int* in_sizes, int n_in,
                              void* d_out, int out_size) {
    const float* x  = (const float*)d_in[0];
    const float* W1 = (const float*)d_in[1];
    const float* b1 = (const float*)d_in[2];
    const float* W2 = (const float*)d_in[3];
    const int*   la = (const int*)d_in[4];
    float* out = (float*)d_out;

    dtnet_prep<<<320, 256>>>(W1, b1, W2);
    cudaFuncSetAttribute(dtnet_mma, cudaFuncAttributeMaxDynamicSharedMemorySize, SMEMB);
    int Btot = in_sizes[0] / 128;   // 131072
    dtnet_mma<<<Btot / 64, 512, SMEMB>>>(x, la, out);
}